// round 10
// baseline (speedup 1.0000x reference)
#include <cuda_runtime.h>
#include <stdint.h>

// RecyclingEmbedder: out[i,j,:] = W[:,bin(d_ij)] + b  (b only if no bin hit)
//
// R9 A/B confirmed .cs streaming stores are worth ~8.5us — restored here.
// New insight: R6 compiled to 36 regs -> only 7 CTAs/SM resident (reg file
// 65536/(36*32)=56 warps), so grid 1184 ran as a 1036-block wave + a 148-block
// straggler wave (occ 62%). R10: __launch_bounds__(256, 8) forces <=32 regs,
// restoring 8 CTAs/SM and one clean wave while keeping the R6 software
// pipeline (next group's bins/ballots computed during the current 16KB burst).

#define N_PTS   1536
#define D_PAIR  128
#define GROUPS_PER_ROW (N_PTS / 32)          // 48
#define NGROUPS (N_PTS * GROUPS_PER_ROW)     // 73728
#define NWARPS_PER_BLOCK 8
#define BLOCK_THREADS (NWARPS_PER_BLOCK * 32)

struct GroupPlan {
    unsigned m15;   // lanes whose row is b-only
    unsigned m0;    // lanes whose row is bin 0
    int      bi;    // this lane's bin (for rare-path shfl)
    int      i, j0; // group coordinates
};

__device__ __forceinline__ GroupPlan plan_group(int g, int lane,
                                                const float* __restrict__ s_x)
{
    GroupPlan pl;
    pl.i  = g / GROUPS_PER_ROW;
    pl.j0 = (g - pl.i * GROUPS_PER_ROW) * 32;
    const int j = pl.j0 + lane;

    // Match reference rounding exactly: no FMA contraction,
    // sum order (dx^2 + dy^2) + dz^2.
    float dx = s_x[pl.i * 3 + 0] - s_x[j * 3 + 0];
    float dy = s_x[pl.i * 3 + 1] - s_x[j * 3 + 1];
    float dz = s_x[pl.i * 3 + 2] - s_x[j * 3 + 2];
    float d  = __fadd_rn(__fadd_rn(__fmul_rn(dx, dx), __fmul_rn(dy, dy)),
                         __fmul_rn(dz, dz));

    int bi = 15;  // default: no bin hit -> b-only row
    #pragma unroll
    for (int k = 0; k < 15; k++) {
        const float e0 = 3.25f + 1.25f * (float)k;
        const float lo = e0 * e0;                        // folded at compile time
        const float e1 = 3.25f + 1.25f * (float)(k + 1);
        const float hi = (k == 14) ? 100000000.0f : e1 * e1;
        if (d > lo && d < hi) bi = k;
    }
    pl.bi  = bi;
    pl.m15 = __ballot_sync(0xffffffffu, bi == 15);
    pl.m0  = __ballot_sync(0xffffffffu, bi == 0);
    return pl;
}

__global__ __launch_bounds__(BLOCK_THREADS, 8)   // force <=32 regs: 8 CTAs/SM
void recycling_embedder_kernel(const float* __restrict__ x,
                               const float* __restrict__ W,
                               const float* __restrict__ b,
                               float* __restrict__ out)
{
    __shared__ float s_table[16 * D_PAIR];   // 8 KB:  row k = W[:,k]+b, row 15 = b
    __shared__ float s_x[N_PTS * 3];         // 18 KB

    const int tid = threadIdx.x;

    // table[k][p] = W[p*15+k] + b[p] for k<15; table[15][p] = b[p].
    for (int idx = tid; idx < 16 * D_PAIR; idx += BLOCK_THREADS) {
        int k = idx >> 7;
        int p = idx & (D_PAIR - 1);
        float v = b[p];
        if (k < 15) v += W[p * 15 + k];
        s_table[idx] = v;
    }
    for (int idx = tid; idx < N_PTS * 3; idx += BLOCK_THREADS) {
        s_x[idx] = x[idx];
    }
    __syncthreads();

    const int lane = tid & 31;
    const int warp = tid >> 5;
    const int gwarp  = blockIdx.x * NWARPS_PER_BLOCK + warp;
    const int nwarps = gridDim.x * NWARPS_PER_BLOCK;

    // Hot rows in registers: row 15 (b only, ~83%) and row 0 (~15%).
    const float4 v15 = *reinterpret_cast<const float4*>(&s_table[15 * D_PAIR + lane * 4]);
    const float4 v0  = *reinterpret_cast<const float4*>(&s_table[ 0 * D_PAIR + lane * 4]);

    if (gwarp >= NGROUPS) return;

    // Software pipeline: plan for group g is ready before its store burst.
    GroupPlan cur = plan_group(gwarp, lane, s_x);

    for (int g = gwarp; g < NGROUPS; g += nwarps) {
        const int gnext = g + nwarps;

        float4* dst = reinterpret_cast<float4*>(
                          out + ((size_t)cur.i * N_PTS + cur.j0) * D_PAIR) + lane;
        const unsigned m15 = cur.m15;
        const unsigned m0  = cur.m0;
        const int      bic = cur.bi;

        // Overlap: compute next group's plan before draining this burst.
        GroupPlan nxt;
        if (gnext < NGROUPS) nxt = plan_group(gnext, lane, s_x);

        // Stream 32 rows (16 KB contiguous). Rare rows (~2%) take a
        // warp-uniform shfl + LDS; the branch is divergence-free.
        #pragma unroll
        for (int p = 0; p < 32; p++) {
            float4 v;
            if ((m15 >> p) & 1u) {
                v = v15;
            } else if ((m0 >> p) & 1u) {
                v = v0;
            } else {
                int bp = __shfl_sync(0xffffffffu, bic, p);
                v = *reinterpret_cast<const float4*>(
                        &s_table[bp * D_PAIR + lane * 4]);
            }
            __stcs(&dst[p * (D_PAIR / 4)], v);   // STG.E.128 streaming
        }

        cur = nxt;
    }
}

extern "C" void kernel_launch(void* const* d_in, const int* in_sizes, int n_in,
                              void* d_out, int out_size)
{
    const float* x = (const float*)d_in[0];   // [1536, 3]
    const float* W = (const float*)d_in[1];   // [128, 15]
    const float* b = (const float*)d_in[2];   // [128]
    float* out = (float*)d_out;               // [1536, 1536, 128]

    // 1184 = 148 SMs * 8 blocks (27KB smem, <=32 regs): one true resident
    // wave; static grid-stride rounds sweep contiguous ~148MB spans chip-wide.
    recycling_embedder_kernel<<<1184, BLOCK_THREADS>>>(x, W, b, out);
}

// round 14
// speedup vs baseline: 1.0797x; 1.0797x over previous
#include <cuda_runtime.h>
#include <stdint.h>

// RecyclingEmbedder: out[i,j,:] = W[:,bin(d_ij)] + b  (b only if no bin hit)
//
// R10 post-mortem: capping to 32 regs raised occ (62->78%) but broke store-
// burst codegen (DRAM 78->74.5%, dur 184->195). Occupancy is NOT the limiter;
// dense front-batched STG runs are. R11 = exact R6 config (best: 184.4us,
// no reg cap, .cs stores, sw-pipelined phase 1) + a warp-uniform fast path:
// ~50% of groups have all 32 rows hot (rows 15/0 only), where the burst
// reduces to SEL + STG per row with no shfl/LDS path in the loop body.

#define N_PTS   1536
#define D_PAIR  128
#define GROUPS_PER_ROW (N_PTS / 32)          // 48
#define NGROUPS (N_PTS * GROUPS_PER_ROW)     // 73728
#define NWARPS_PER_BLOCK 8
#define BLOCK_THREADS (NWARPS_PER_BLOCK * 32)

struct GroupPlan {
    unsigned m15;   // lanes whose row is b-only
    unsigned m0;    // lanes whose row is bin 0
    int      bi;    // this lane's bin (for rare-path shfl)
    int      i, j0; // group coordinates
};

__device__ __forceinline__ GroupPlan plan_group(int g, int lane,
                                                const float* __restrict__ s_x)
{
    GroupPlan pl;
    pl.i  = g / GROUPS_PER_ROW;
    pl.j0 = (g - pl.i * GROUPS_PER_ROW) * 32;
    const int j = pl.j0 + lane;

    // Match reference rounding exactly: no FMA contraction,
    // sum order (dx^2 + dy^2) + dz^2.
    float dx = s_x[pl.i * 3 + 0] - s_x[j * 3 + 0];
    float dy = s_x[pl.i * 3 + 1] - s_x[j * 3 + 1];
    float dz = s_x[pl.i * 3 + 2] - s_x[j * 3 + 2];
    float d  = __fadd_rn(__fadd_rn(__fmul_rn(dx, dx), __fmul_rn(dy, dy)),
                         __fmul_rn(dz, dz));

    int bi = 15;  // default: no bin hit -> b-only row
    #pragma unroll
    for (int k = 0; k < 15; k++) {
        const float e0 = 3.25f + 1.25f * (float)k;
        const float lo = e0 * e0;                        // folded at compile time
        const float e1 = 3.25f + 1.25f * (float)(k + 1);
        const float hi = (k == 14) ? 100000000.0f : e1 * e1;
        if (d > lo && d < hi) bi = k;
    }
    pl.bi  = bi;
    pl.m15 = __ballot_sync(0xffffffffu, bi == 15);
    pl.m0  = __ballot_sync(0xffffffffu, bi == 0);
    return pl;
}

__global__ __launch_bounds__(BLOCK_THREADS)   // no min-CTA cap: let regs float (R6 codegen)
void recycling_embedder_kernel(const float* __restrict__ x,
                               const float* __restrict__ W,
                               const float* __restrict__ b,
                               float* __restrict__ out)
{
    __shared__ float s_table[16 * D_PAIR];   // 8 KB:  row k = W[:,k]+b, row 15 = b
    __shared__ float s_x[N_PTS * 3];         // 18 KB

    const int tid = threadIdx.x;

    // table[k][p] = W[p*15+k] + b[p] for k<15; table[15][p] = b[p].
    for (int idx = tid; idx < 16 * D_PAIR; idx += BLOCK_THREADS) {
        int k = idx >> 7;
        int p = idx & (D_PAIR - 1);
        float v = b[p];
        if (k < 15) v += W[p * 15 + k];
        s_table[idx] = v;
    }
    for (int idx = tid; idx < N_PTS * 3; idx += BLOCK_THREADS) {
        s_x[idx] = x[idx];
    }
    __syncthreads();

    const int lane = tid & 31;
    const int warp = tid >> 5;
    const int gwarp  = blockIdx.x * NWARPS_PER_BLOCK + warp;
    const int nwarps = gridDim.x * NWARPS_PER_BLOCK;

    // Hot rows in registers: row 15 (b only, ~83%) and row 0 (~15%).
    const float4 v15 = *reinterpret_cast<const float4*>(&s_table[15 * D_PAIR + lane * 4]);
    const float4 v0  = *reinterpret_cast<const float4*>(&s_table[ 0 * D_PAIR + lane * 4]);

    if (gwarp >= NGROUPS) return;

    // Software pipeline: plan for group g is ready before its store burst.
    GroupPlan cur = plan_group(gwarp, lane, s_x);

    for (int g = gwarp; g < NGROUPS; g += nwarps) {
        const int gnext = g + nwarps;

        float4* dst = reinterpret_cast<float4*>(
                          out + ((size_t)cur.i * N_PTS + cur.j0) * D_PAIR) + lane;
        const unsigned m15 = cur.m15;
        const unsigned m0  = cur.m0;
        const int      bic = cur.bi;

        // Overlap: compute next group's plan before draining this burst.
        GroupPlan nxt;
        if (gnext < NGROUPS) nxt = plan_group(gnext, lane, s_x);

        if ((m15 | m0) == 0xffffffffu) {
            // Fast path (~50% of groups): every row is hot. Pure SEL + STG —
            // densest possible store burst.
            #pragma unroll
            for (int p = 0; p < 32; p++) {
                float4 v = ((m15 >> p) & 1u) ? v15 : v0;
                __stcs(&dst[p * (D_PAIR / 4)], v);   // STG.E.128 streaming
            }
        } else {
            // General path: rare rows (~2% of all rows) take a warp-uniform
            // shfl + LDS; branch is divergence-free.
            #pragma unroll
            for (int p = 0; p < 32; p++) {
                float4 v;
                if ((m15 >> p) & 1u) {
                    v = v15;
                } else if ((m0 >> p) & 1u) {
                    v = v0;
                } else {
                    int bp = __shfl_sync(0xffffffffu, bic, p);
                    v = *reinterpret_cast<const float4*>(
                            &s_table[bp * D_PAIR + lane * 4]);
                }
                __stcs(&dst[p * (D_PAIR / 4)], v);   // STG.E.128 streaming
            }
        }

        cur = nxt;
    }
}

extern "C" void kernel_launch(void* const* d_in, const int* in_sizes, int n_in,
                              void* d_out, int out_size)
{
    const float* x = (const float*)d_in[0];   // [1536, 3]
    const float* W = (const float*)d_in[1];   // [128, 15]
    const float* b = (const float*)d_in[2];   // [128]
    float* out = (float*)d_out;               // [1536, 1536, 128]

    // 1184 = 148 SMs * 8 blocks (27KB smem each): static grid-stride rounds
    // sweep contiguous ~148MB output spans chip-wide (proven best mapping).
    recycling_embedder_kernel<<<1184, BLOCK_THREADS>>>(x, W, b, out);
}